// round 5
// baseline (speedup 1.0000x reference)
#include <cuda_runtime.h>
#include <cstdint>

// ---------------------------------------------------------------------------
// PreActBlock_conv_Q — exact-integer IMMA formulation (mma.sync m16n8k32 s8).
//   act  a = j/15 (store j in int8, 0..15)
//   wq   w = Mw*(2q-15)/15 (store 2q-15 in int8)
//   conv y = (Mw/225) * S,  S exact int32 from IMMA.
// Padded NHWC activations [16][58][58][256] + 128 guard rows each side ->
// no bounds checks in the GEMM mainloop.
// Fusions: BN1 stats inside conv0 epilogue; scale+shortcut+NCHW transpose
// inside conv1 epilogue. 3-stage cp.async pipeline, compute-then-prefetch
// (two barriers per chunk: no writer can touch a buffer before all its
// readers pass the second barrier).
// ---------------------------------------------------------------------------

#define CCH     256
#define HWSZ    3136
#define PW      58
#define PSP     3364
#define MPAD    53824           // 16*3364
#define MTILES  421
#define MROWS   53888           // 421*128
#define GUARD   128
#define KW_ELEMS 589824
#define CHUNKS  18              // K = 18 * 128 bytes
#define STAGE_B 32768
#define SMEM_DYN 98304          // 3 stages (also covers 128x132 float transpose)

__device__ signed char g_a0[(MPAD + 2 * GUARD) * CCH];
__device__ signed char g_a1[(MPAD + 2 * GUARD) * CCH];
__device__ int         g_y0[(size_t)MROWS * CCH];
__device__ signed char g_wq0[KW_ELEMS];
__device__ signed char g_wq1[KW_ELEMS];
__device__ int         g_wmaxbits[2];
__device__ float       g_mean0[CCH], g_rstd0[CCH];
__device__ long long   g_sum1[CCH], g_sumsq1[CCH];
__device__ float       g_mean1[CCH], g_rstd1[CCH];

// ---------------------------------------------------------------------------
__device__ __forceinline__ uint32_t smem_u32(const void* p) {
    uint32_t a;
    asm("{ .reg .u64 t; cvta.to.shared.u64 t, %1; cvt.u32.u64 %0, t; }"
        : "=r"(a) : "l"(p));
    return a;
}
__device__ __forceinline__ void cp16(uint32_t dst, const void* src) {
    asm volatile("cp.async.cg.shared.global [%0], [%1], 16;"
                 :: "r"(dst), "l"(src) : "memory");
}
__device__ __forceinline__ void ldx4(uint32_t* r, uint32_t addr) {
    asm volatile("ldmatrix.sync.aligned.m8n8.x4.shared.b16 {%0,%1,%2,%3}, [%4];"
                 : "=r"(r[0]), "=r"(r[1]), "=r"(r[2]), "=r"(r[3]) : "r"(addr));
}
__device__ __forceinline__ void imma(int* d, const uint32_t* a, uint32_t b0, uint32_t b1) {
    asm volatile(
        "mma.sync.aligned.m16n8k32.row.col.s32.s8.s8.s32 "
        "{%0,%1,%2,%3}, {%4,%5,%6,%7}, {%8,%9}, {%0,%1,%2,%3};"
        : "+r"(d[0]), "+r"(d[1]), "+r"(d[2]), "+r"(d[3])
        : "r"(a[0]), "r"(a[1]), "r"(a[2]), "r"(a[3]), "r"(b0), "r"(b1));
}

__device__ __forceinline__ bool row_valid(int p) {
    if (p >= MPAD) return false;
    int rem = p % PSP;
    int hp = rem / PW, wp = rem - hp * PW;
    return (hp >= 1) && (hp <= 56) && (wp >= 1) && (wp <= 56);
}

// ---------------------------------------------------------------------------
__global__ void init_kernel() {
    int t = threadIdx.x;
    if (t < 2) g_wmaxbits[t] = 0;
    g_sum1[t] = 0; g_sumsq1[t] = 0;
}

__global__ void wabsmax_kernel(const float* __restrict__ w, int slot) {
    int i = blockIdx.x * blockDim.x + threadIdx.x;
    float m = 0.0f;
    for (; i < KW_ELEMS; i += gridDim.x * blockDim.x)
        m = fmaxf(m, fabsf(tanhf(w[i])));
#pragma unroll
    for (int o = 16; o; o >>= 1) m = fmaxf(m, __shfl_xor_sync(~0u, m, o));
    if ((threadIdx.x & 31) == 0) atomicMax(&g_wmaxbits[slot], __float_as_int(m));
}

__global__ void wquant_kernel(const float* __restrict__ w, int slot) {
    int idx = blockIdx.x * 256 + threadIdx.x;
    if (idx >= KW_ELEMS) return;
    float M = __int_as_float(g_wmaxbits[slot]);
    float t = tanhf(w[idx]);
    float wn = __fdiv_rn(t, 2.0f * M) + 0.5f;
    int q = __float2int_rn(wn * 15.0f);
    int cout = idx / 2304;
    int rem  = idx - cout * 2304;
    int cin  = rem / 9;
    int r    = rem - cin * 9;
    (slot == 0 ? g_wq0 : g_wq1)[cout * 2304 + r * 256 + cin] = (signed char)(2 * q - 15);
}

__global__ void bn0_stats_kernel(const float* __restrict__ x) {
    int c = blockIdx.x;
    double s = 0.0, ss = 0.0;
    for (int n = 0; n < 16; n++) {
        const float* p = x + ((size_t)(n * CCH + c)) * HWSZ;
        for (int i = threadIdx.x; i < HWSZ; i += blockDim.x) {
            float v = p[i]; s += v; ss += (double)v * v;
        }
    }
    __shared__ double sh[256], sh2[256];
    sh[threadIdx.x] = s; sh2[threadIdx.x] = ss;
    __syncthreads();
    for (int o = 128; o; o >>= 1) {
        if (threadIdx.x < o) { sh[threadIdx.x] += sh[threadIdx.x+o]; sh2[threadIdx.x] += sh2[threadIdx.x+o]; }
        __syncthreads();
    }
    if (threadIdx.x == 0) {
        double mean = sh[0] / 50176.0;
        double var  = sh2[0] / 50176.0 - mean * mean;
        g_mean0[c] = (float)mean;
        g_rstd0[c] = (float)(1.0 / sqrt(var + 1e-5));
    }
}

// BN0+relu+quant, NCHW -> padded NHWC int8
__global__ void act0_kernel(const float* __restrict__ x,
                            const float* __restrict__ gamma,
                            const float* __restrict__ beta) {
    __shared__ signed char tile[32][33];
    int n = blockIdx.z, c0 = blockIdx.y * 32, hw0 = blockIdx.x * 32;
    int tx = threadIdx.x, ty = threadIdx.y;
#pragma unroll
    for (int i = 0; i < 4; i++) {
        int c = c0 + ty + 8 * i;
        float v  = x[((size_t)(n * CCH + c)) * HWSZ + hw0 + tx];
        float xn = (v - g_mean0[c]) * g_rstd0[c] * gamma[c] + beta[c];
        float r  = fminf(fmaxf(xn, 0.0f), 1.0f);
        tile[ty + 8 * i][tx] = (signed char)__float2int_rn(r * 15.0f);
    }
    __syncthreads();
#pragma unroll
    for (int i = 0; i < 4; i++) {
        int hw = hw0 + ty + 8 * i;
        int h = hw / 56, w = hw - h * 56;
        int mrow = n * PSP + (h + 1) * PW + (w + 1);
        g_a0[(size_t)(mrow + GUARD) * CCH + c0 + tx] = tile[tx][ty + 8 * i];
    }
}

// ---------------------------------------------------------------------------
// IMMA implicit-GEMM conv. CTA tile 128x128, K = 18 x 128B, 3-stage cp.async.
// epi=0: write int32 Y + fused exact BN1 stats.
// epi=1: smem-transposed NCHW epilogue: Out = S*ys + Xin.
// ---------------------------------------------------------------------------
__global__ void __launch_bounds__(256, 2) conv_imma_kernel(
    const signed char* __restrict__ A,   // guard-offset padded NHWC base
    const signed char* __restrict__ W,   // [256][2304]
    int* __restrict__ Y,
    const float* __restrict__ Xin,
    float* __restrict__ Out,
    int epi)
{
    extern __shared__ char smem[];
    const uint32_t sb = smem_u32(smem);
    const int tid = threadIdx.x;
    const int lane = tid & 31, wid = tid >> 5;
    const int warp_m = wid & 3, warp_n = wid >> 2;
    const int mbase = blockIdx.x * 128;
    const int nbase = blockIdx.y * 128;

    const int cr = tid >> 1;
    const int seg0 = (tid & 1) * 4;

    int acc[2][8][4];
#pragma unroll
    for (int mt = 0; mt < 2; mt++)
#pragma unroll
        for (int nt = 0; nt < 8; nt++)
#pragma unroll
            for (int v = 0; v < 4; v++) acc[mt][nt][v] = 0;

    int a_row[2], a_sw[2];
#pragma unroll
    for (int mt = 0; mt < 2; mt++) {
        a_row[mt] = warp_m * 32 + mt * 16 + ((lane >> 3) & 1) * 8 + (lane & 7);
        a_sw[mt]  = a_row[mt] & 7;
    }
    const int a_ch = lane >> 4;
    int b_row[4], b_sw[4];
#pragma unroll
    for (int jp = 0; jp < 4; jp++) {
        b_row[jp] = warp_n * 64 + jp * 16 + (lane >> 4) * 8 + (lane & 7);
        b_sw[jp]  = b_row[jp] & 7;
    }
    const int b_ch = (lane >> 3) & 1;

#define LOAD_CHUNK(s, buf) do {                                               \
    int _r = (s) >> 1;                                                        \
    int _off = (_r / 3 - 1) * PW + (_r % 3) - 1;                              \
    int _cinb = ((s) & 1) << 7;                                               \
    const signed char* _sa = A + (size_t)(mbase + _off + cr) * CCH + _cinb;   \
    uint32_t _da = sb + (buf) * (uint32_t)STAGE_B + cr * 128u;                \
    const signed char* _sw = W + (size_t)(nbase + cr) * 2304 + (s) * 128;     \
    uint32_t _dw = _da + 16384u;                                              \
    _Pragma("unroll")                                                         \
    for (int _i = 0; _i < 4; _i++) {                                          \
        int _seg = seg0 + _i;                                                 \
        cp16(_da + (uint32_t)((_seg ^ (cr & 7)) << 4), _sa + _seg * 16);      \
        cp16(_dw + (uint32_t)((_seg ^ (cr & 7)) << 4), _sw + _seg * 16);      \
    }                                                                         \
    asm volatile("cp.async.commit_group;" ::: "memory");                      \
} while (0)

#define COMPUTE_CHUNK(buf) do {                                               \
    uint32_t _As = sb + (buf) * (uint32_t)STAGE_B;                            \
    uint32_t _Bs = _As + 16384u;                                              \
    _Pragma("unroll")                                                         \
    for (int kc = 0; kc < 4; kc++) {                                          \
        uint32_t afr[2][4];                                                   \
        _Pragma("unroll")                                                     \
        for (int mt = 0; mt < 2; mt++) {                                      \
            int ch = 2 * kc + a_ch;                                           \
            ldx4(afr[mt], _As + a_row[mt] * 128u +                            \
                          (uint32_t)((ch ^ a_sw[mt]) << 4));                  \
        }                                                                     \
        _Pragma("unroll")                                                     \
        for (int jp = 0; jp < 4; jp++) {                                      \
            uint32_t bfr[4];                                                  \
            int ch = 2 * kc + b_ch;                                           \
            ldx4(bfr, _Bs + b_row[jp] * 128u +                                \
                      (uint32_t)((ch ^ b_sw[jp]) << 4));                      \
            _Pragma("unroll")                                                 \
            for (int mt = 0; mt < 2; mt++) {                                  \
                imma(acc[mt][2 * jp],     afr[mt], bfr[0], bfr[1]);           \
                imma(acc[mt][2 * jp + 1], afr[mt], bfr[2], bfr[3]);           \
            }                                                                 \
        }                                                                     \
    }                                                                         \
} while (0)

    // prologue: fill all 3 stages
    LOAD_CHUNK(0, 0);
    LOAD_CHUNK(1, 1);
    LOAD_CHUNK(2, 2);

    for (int s = 0; s < CHUNKS; s++) {
        // wait until chunk s has landed (outstanding-after = min(2, CHUNKS-1-s))
        if (s + 2 < CHUNKS)
            asm volatile("cp.async.wait_group 2;" ::: "memory");
        else if (s + 1 < CHUNKS)
            asm volatile("cp.async.wait_group 1;" ::: "memory");
        else
            asm volatile("cp.async.wait_group 0;" ::: "memory");
        __syncthreads();
        COMPUTE_CHUNK(s % 3);
        __syncthreads();              // all readers of buffer s%3 are done
        if (s + 3 < CHUNKS)
            LOAD_CHUNK(s + 3, s % 3); // safe: overwrites fully-consumed buffer
    }
    __syncthreads();   // protect smem reuse in epilogue

    const int erow = mbase + warp_m * 32 + (lane >> 2);
    const int ecol = warp_n * 64 + (lane & 3) * 2;     // local channel

    if (epi == 0) {
        // ---- store int32 Y ----
#pragma unroll
        for (int mt = 0; mt < 2; mt++) {
#pragma unroll
            for (int nt = 0; nt < 8; nt++) {
                int r0 = erow + mt * 16;
                int c  = nbase + ecol + nt * 8;
                *(int2*)&Y[(size_t)r0 * CCH + c]       = make_int2(acc[mt][nt][0], acc[mt][nt][1]);
                *(int2*)&Y[(size_t)(r0 + 8) * CCH + c] = make_int2(acc[mt][nt][2], acc[mt][nt][3]);
            }
        }
        // ---- fused exact BN1 stats ----
        unsigned long long* ssum = (unsigned long long*)smem;      // [128]
        unsigned long long* ssq  = ssum + 128;                     // [128]
        ((unsigned long long*)smem)[tid] = 0ull;
        __syncthreads();
        bool vr[4];
#pragma unroll
        for (int g = 0; g < 4; g++)
            vr[g] = row_valid(erow + (g >> 1) * 16 + (g & 1) * 8);
#pragma unroll
        for (int nt = 0; nt < 8; nt++) {
#pragma unroll
            for (int j = 0; j < 2; j++) {
                long long s = 0, q = 0;
#pragma unroll
                for (int mt = 0; mt < 2; mt++) {
                    int v0 = acc[mt][nt][j], v1 = acc[mt][nt][2 + j];
                    if (vr[2 * mt])     { s += v0; q += (long long)v0 * v0; }
                    if (vr[2 * mt + 1]) { s += v1; q += (long long)v1 * v1; }
                }
                int chl = ecol + nt * 8 + j;
                atomicAdd(&ssum[chl], (unsigned long long)s);
                atomicAdd(&ssq[chl],  (unsigned long long)q);
            }
        }
        __syncthreads();
        if (tid < 128)
            atomicAdd((unsigned long long*)&g_sum1[nbase + tid], ssum[tid]);
        else
            atomicAdd((unsigned long long*)&g_sumsq1[nbase + tid - 128], ssq[tid - 128]);
    } else {
        // ---- transpose + scale + shortcut, NCHW output ----
        float* T = (float*)smem;                       // [128][132]
#pragma unroll
        for (int mt = 0; mt < 2; mt++)
#pragma unroll
            for (int nt = 0; nt < 8; nt++)
#pragma unroll
                for (int v = 0; v < 4; v++) {
                    int cl = ecol + nt * 8 + (v & 1);
                    int ml = warp_m * 32 + mt * 16 + (v >> 1) * 8 + (lane >> 2);
                    T[cl * 132 + ml] = (float)acc[mt][nt][v];
                }
        __syncthreads();
        float ys = __int_as_float(g_wmaxbits[1]) * (1.0f / 225.0f);
        int m = tid & 127, ch2 = tid >> 7;
        int p = mbase + m;
        bool valid = row_valid(p);
        size_t obase = 0;
        if (valid) {
            int n = p / PSP, rem = p - n * PSP;
            int hp = rem / PW, wp = rem - hp * PW;
            obase = ((size_t)n * CCH) * HWSZ + (size_t)(hp - 1) * 56 + (wp - 1);
        }
#pragma unroll 8
        for (int ci = 0; ci < 64; ci++) {
            int c = 2 * ci + ch2;
            if (valid) {
                size_t o = obase + (size_t)(nbase + c) * HWSZ;
                Out[o] = T[c * 132 + m] * ys + Xin[o];
            }
        }
    }
}

__global__ void bn1_final_kernel() {
    int c = threadIdx.x;
    double ys   = (double)__int_as_float(g_wmaxbits[0]) / 225.0;
    double mean = ys * (double)g_sum1[c] / 50176.0;
    double e2   = ys * ys * (double)g_sumsq1[c] / 50176.0;
    g_mean1[c] = (float)mean;
    g_rstd1[c] = (float)(1.0 / sqrt(e2 - mean * mean + 1e-5));
}

// BN1+relu+quant (valid cells only; halo/guard stay zero-initialized)
__global__ void act1_kernel(const float* __restrict__ g1,
                            const float* __restrict__ b1) {
    int idx = blockIdx.x * 256 + threadIdx.x;   // MPAD*256
    int mrow = idx >> 8, c = idx & 255;
    int rem = mrow % PSP;
    int hp = rem / PW, wp = rem - hp * PW;
    if ((hp >= 1) && (hp <= 56) && (wp >= 1) && (wp <= 56)) {
        float ys = __int_as_float(g_wmaxbits[0]) * (1.0f / 225.0f);
        float y  = (float)g_y0[idx] * ys;
        float xn = (y - g_mean1[c]) * g_rstd1[c] * g1[c] + b1[c];
        float r  = fminf(fmaxf(xn, 0.0f), 1.0f);
        g_a1[(size_t)(mrow + GUARD) * CCH + c] = (signed char)__float2int_rn(r * 15.0f);
    }
}

// ---------------------------------------------------------------------------
extern "C" void kernel_launch(void* const* d_in, const int* in_sizes, int n_in,
                              void* d_out, int out_size) {
    const float* x  = (const float*)d_in[0];
    const float* g0 = (const float*)d_in[1];
    const float* b0 = (const float*)d_in[2];
    const float* w0 = (const float*)d_in[3];
    const float* g1 = (const float*)d_in[4];
    const float* b1 = (const float*)d_in[5];
    const float* w1 = (const float*)d_in[6];
    float* out = (float*)d_out;

    void *pa0, *pa1, *pw0, *pw1, *py0;
    cudaGetSymbolAddress(&pa0, g_a0);
    cudaGetSymbolAddress(&pa1, g_a1);
    cudaGetSymbolAddress(&pw0, g_wq0);
    cudaGetSymbolAddress(&pw1, g_wq1);
    cudaGetSymbolAddress(&py0, g_y0);

    cudaFuncSetAttribute(conv_imma_kernel,
                         cudaFuncAttributeMaxDynamicSharedMemorySize, SMEM_DYN);

    init_kernel<<<1, 256>>>();
    wabsmax_kernel<<<256, 256>>>(w0, 0);
    wabsmax_kernel<<<256, 256>>>(w1, 1);
    wquant_kernel<<<(KW_ELEMS + 255) / 256, 256>>>(w0, 0);
    wquant_kernel<<<(KW_ELEMS + 255) / 256, 256>>>(w1, 1);
    bn0_stats_kernel<<<256, 256>>>(x);
    act0_kernel<<<dim3(98, 8, 16), dim3(32, 8)>>>(x, g0, b0);
    conv_imma_kernel<<<dim3(MTILES, 2), 256, SMEM_DYN>>>(
        (const signed char*)pa0 + (size_t)GUARD * CCH,
        (const signed char*)pw0, (int*)py0, nullptr, nullptr, 0);
    bn1_final_kernel<<<1, 256>>>();
    act1_kernel<<<MPAD, 256>>>(g1, b1);
    conv_imma_kernel<<<dim3(MTILES, 2), 256, SMEM_DYN>>>(
        (const signed char*)pa1 + (size_t)GUARD * CCH,
        (const signed char*)pw1, (int*)py0, x, out, 1);
}